// round 1
// baseline (speedup 1.0000x reference)
#include <cuda_runtime.h>
#include <cstdint>

#define B 8
#define C 128
#define H 256
#define W 256
#define HW (H*W)        // 65536
#define HW4 (HW/4)      // 16384

// scratch: pooled max map and attention map, [B, H, W]
__device__ float g_pooled[B * HW];
__device__ float g_attn[B * HW];

// ---------------------------------------------------------------------------
// Kernel 1: pooled[b,h,w] = max_c x[b,c,h,w]
// One thread per float4 of spatial pixels. 131072 threads total.
// Per-channel stride = HW floats (64KB) but each warp's loads are coalesced.
// ---------------------------------------------------------------------------
__global__ void pool_max_kernel(const float* __restrict__ x) {
    int t = blockIdx.x * blockDim.x + threadIdx.x;   // float4-pixel index, < B*HW4
    int b   = t >> 14;            // / HW4
    int hw4 = t & (HW4 - 1);
    const float4* p = reinterpret_cast<const float4*>(x) + (size_t)b * C * HW4 + hw4;

    float4 m = p[0];
    // unroll for MLP: 4 independent loads in flight
    #pragma unroll 4
    for (int c = 1; c < C; ++c) {
        float4 v = p[(size_t)c * HW4];
        m.x = fmaxf(m.x, v.x);
        m.y = fmaxf(m.y, v.y);
        m.z = fmaxf(m.z, v.z);
        m.w = fmaxf(m.w, v.w);
    }
    reinterpret_cast<float4*>(g_pooled)[t] = m;
}

// ---------------------------------------------------------------------------
// Kernel 2: attn = sigmoid(conv7x7(pooled) + bias), zero padding 3.
// Tile 64x16 outputs per block, 256 threads, smem halo tile 70x22.
// ---------------------------------------------------------------------------
#define TW 64
#define TH 16

__global__ void conv_sigmoid_kernel(const float* __restrict__ cw,
                                    const float* __restrict__ cb) {
    __shared__ float s[TH + 6][TW + 6];
    const int b   = blockIdx.z;
    const int tx0 = blockIdx.x * TW;
    const int ty0 = blockIdx.y * TH;
    const float* pb = g_pooled + b * HW;

    // cooperative halo load with zero padding
    for (int i = threadIdx.x; i < (TH + 6) * (TW + 6); i += blockDim.x) {
        int ly = i / (TW + 6);
        int lx = i - ly * (TW + 6);
        int gy = ty0 + ly - 3;
        int gx = tx0 + lx - 3;
        float v = 0.0f;
        if (gy >= 0 && gy < H && gx >= 0 && gx < W) v = pb[gy * W + gx];
        s[ly][lx] = v;
    }
    __syncthreads();

    float wr[49];
    #pragma unroll
    for (int i = 0; i < 49; ++i) wr[i] = __ldg(&cw[i]);
    const float bias = __ldg(&cb[0]);

    const int lx  = threadIdx.x & (TW - 1);
    const int ly0 = threadIdx.x >> 6;        // 0..3

    #pragma unroll
    for (int r = 0; r < TH; r += 4) {
        const int ly = ly0 + r;
        float acc = bias;
        #pragma unroll
        for (int i = 0; i < 7; ++i)
            #pragma unroll
            for (int j = 0; j < 7; ++j)
                acc = fmaf(s[ly + i][lx + j], wr[i * 7 + j], acc);
        // sigmoid
        float sg = 1.0f / (1.0f + __expf(-acc));
        g_attn[b * HW + (ty0 + ly) * W + tx0 + lx] = sg;
    }
}

// ---------------------------------------------------------------------------
// Kernel 3: out[b,c,h,w] = x[b,c,h,w] * attn[b,h,w]. Pure streaming, float4.
// attn is 2MB and reused 128x -> stays L2-resident.
// ---------------------------------------------------------------------------
__global__ void mul_kernel(const float* __restrict__ x, float* __restrict__ out) {
    size_t i = (size_t)blockIdx.x * blockDim.x + threadIdx.x;   // float4 index
    int hw4 = (int)(i & (HW4 - 1));
    int b   = (int)(i >> 21);                 // i / (C*HW4) = i / 2^21
    float4 a = reinterpret_cast<const float4*>(g_attn)[(size_t)b * HW4 + hw4];
    float4 v = reinterpret_cast<const float4*>(x)[i];
    v.x *= a.x; v.y *= a.y; v.z *= a.z; v.w *= a.w;
    reinterpret_cast<float4*>(out)[i] = v;
}

// ---------------------------------------------------------------------------
extern "C" void kernel_launch(void* const* d_in, const int* in_sizes, int n_in,
                              void* d_out, int out_size) {
    const float* x  = (const float*)d_in[0];
    const float* cw = (const float*)d_in[1];   // [1,1,7,7] = 49 floats
    const float* cb = (const float*)d_in[2];   // [1]
    float* out = (float*)d_out;

    // Kernel 1: B*HW4 = 131072 threads
    pool_max_kernel<<<(B * HW4) / 256, 256>>>(x);

    // Kernel 2: grid (W/TW, H/TH, B) = (4, 16, 8)
    dim3 g2(W / TW, H / TH, B);
    conv_sigmoid_kernel<<<g2, 256>>>(cw, cb);

    // Kernel 3: B*C*HW4 = 16777216 float4s
    mul_kernel<<<(size_t)(B * C * HW4) / 256, 256>>>(x, out);
}